// round 6
// baseline (speedup 1.0000x reference)
#include <cuda_runtime.h>

#define NUM_SEG   32
#define MUL       128
#define D         3
#define NUM_PATHS 64
#define SEG_ELEMS (MUL * D)              // 384 floats per segment
#define ROW_ELEMS (NUM_SEG * SEG_ELEMS)  // 12288 floats per batch row

__global__ __launch_bounds__(128, 12)
void ftp3_main(const float* __restrict__ x0,
               const float* __restrict__ x1,
               const float* __restrict__ coeff,
               const int*   __restrict__ idx0,
               const int*   __restrict__ idx1,
               const int*   __restrict__ idx2,
               float*       __restrict__ out)
{
    // M padded to 12 floats/path -> LDS.128 broadcast reads.
    __shared__ __align__(16) float M[NUM_PATHS * 12];
    __shared__ int s_idx2[NUM_PATHS];
    __shared__ int s_off0[NUM_PATHS + 1];     // +1 sentinel for prefetch
    __shared__ int s_out[NUM_PATHS];          // segment-boundary output offset or -1
    __shared__ int s_emptyoff[NUM_SEG];       // offset to zero-fill, or -1

    const int t = threadIdx.x;                // one u per thread
    const int b = blockIdx.x;                 // one batch row per CTA

    if (t < NUM_PATHS) s_idx2[t] = idx2[t];
    if (t == 0)        s_off0[NUM_PATHS] = 0; // sentinel (any valid offset)
    __syncthreads();

    // In-CTA schedule: stable counting-rank of path t by key idx2 (parallel).
    if (t < NUM_PATHS) {
        const int p   = t;
        const int key = s_idx2[p];
        int  r    = 0;
        bool last = true;
        #pragma unroll
        for (int q = 0; q < NUM_PATHS; ++q) {
            const int kq = s_idx2[q];
            r    += (kq < key) | ((kq == key) & (q < p));
            last &= !((kq == key) & (q > p));
        }
        s_off0[r] = idx0[p] * SEG_ELEMS;
        s_out[r]  = last ? key * SEG_ELEMS : -1;

        // M[r][i][k] = sum_j x1[b, idx1[p], j] * coeff[p,i,j,k]
        const float* c   = coeff + p * 27;
        const float* x1b = x1 + (size_t)b * (NUM_SEG * D) + idx1[p] * D;
        const float j0 = x1b[0], j1 = x1b[1], j2 = x1b[2];
        #pragma unroll
        for (int i = 0; i < 3; ++i)
            #pragma unroll
            for (int k = 0; k < 3; ++k)
                M[r * 12 + i * 3 + k] =
                    j0 * c[i * 9 + 0 * 3 + k] +
                    j1 * c[i * 9 + 1 * 3 + k] +
                    j2 * c[i * 9 + 2 * 3 + k];
        M[r * 12 +  9] = 0.f;
        M[r * 12 + 10] = 0.f;
        M[r * 12 + 11] = 0.f;
    }
    if (t < NUM_SEG) {
        int c = 0;
        #pragma unroll
        for (int q = 0; q < NUM_PATHS; ++q) c += (s_idx2[q] == t);
        s_emptyoff[t] = (c == 0) ? t * SEG_ELEMS : -1;
    }
    __syncthreads();

    const float*  x0b  = x0  + (size_t)b * ROW_ELEMS;
    float*        outb = out + (size_t)b * ROW_ELEMS;
    const float4* M4   = (const float4*)M;
    const int u3 = t * 3;

    // Software-pipelined flat path loop: prefetch path q+1 while computing q.
    const float* xs = x0b + s_off0[0] + u3;
    float a0 = xs[0], a1 = xs[1], a2 = xs[2];
    float f0 = 0.f, f1 = 0.f, f2 = 0.f;

    #pragma unroll 8
    for (int q = 0; q < NUM_PATHS; ++q) {
        const float* xn = x0b + s_off0[q + 1] + u3;   // sentinel-safe
        const float n0 = xn[0];
        const float n1 = xn[1];
        const float n2 = xn[2];

        const float4 m0 = M4[q * 3 + 0];   // M00 M01 M02 M10
        const float4 m1 = M4[q * 3 + 1];   // M11 M12 M20 M21
        const float4 m2 = M4[q * 3 + 2];   // M22 0 0 0
        f0 += a0 * m0.x + a1 * m0.w + a2 * m1.z;
        f1 += a0 * m0.y + a1 * m1.x + a2 * m1.w;
        f2 += a0 * m0.z + a1 * m1.y + a2 * m2.x;

        const int oo = s_out[q];
        if (oo >= 0) {
            float* o = outb + oo + u3;
            o[0] = f0; o[1] = f1; o[2] = f2;
            f0 = 0.f; f1 = 0.f; f2 = 0.f;
        }
        a0 = n0; a1 = n1; a2 = n2;
    }

    // Zero-fill segments with no paths (output buffer is poisoned).
    #pragma unroll
    for (int s = 0; s < NUM_SEG; ++s) {
        const int eo = s_emptyoff[s];
        if (eo >= 0) {
            float* o = outb + eo + u3;
            o[0] = 0.f; o[1] = 0.f; o[2] = 0.f;
        }
    }
}

extern "C" void kernel_launch(void* const* d_in, const int* in_sizes, int n_in,
                              void* d_out, int out_size)
{
    const float* x0    = (const float*)d_in[0];  // (2048, 12288)
    const float* x1    = (const float*)d_in[1];  // (2048, 96)
    const float* coeff = (const float*)d_in[2];  // (64, 27)
    const int*   idx0  = (const int*)d_in[3];
    const int*   idx1  = (const int*)d_in[4];
    const int*   idx2  = (const int*)d_in[5];
    float*       out   = (float*)d_out;          // (2048, 12288)

    const int batch = in_sizes[0] / ROW_ELEMS;   // 2048

    ftp3_main<<<batch, 128>>>(x0, x1, coeff, idx0, idx1, idx2, out);
}

// round 7
// speedup vs baseline: 1.1120x; 1.1120x over previous
#include <cuda_runtime.h>

#define NUM_SEG   32
#define MUL       128
#define D         3
#define NUM_PATHS 64
#define SEG_ELEMS (MUL * D)              // 384 floats per segment
#define ROW_ELEMS (NUM_SEG * SEG_ELEMS)  // 12288 floats per batch row

__global__ __launch_bounds__(128)
void ftp3_main(const float* __restrict__ x0,
               const float* __restrict__ x1,
               const float* __restrict__ coeff,
               const int*   __restrict__ idx0,
               const int*   __restrict__ idx1,
               const int*   __restrict__ idx2,
               float*       __restrict__ out)
{
    // M padded to 12 floats/path -> LDS.128 broadcast reads.
    __shared__ __align__(16) float M[NUM_PATHS * 12];
    __shared__ int s_idx2[NUM_PATHS];
    __shared__ int s_off0[NUM_PATHS];
    __shared__ int s_out[NUM_PATHS];          // segment-boundary output offset or -1
    __shared__ int s_emptyoff[NUM_SEG];       // offset to zero-fill, or -1

    const int t = threadIdx.x;                // one u per thread
    const int b = blockIdx.x;                 // one batch row per CTA

    if (t < NUM_PATHS) s_idx2[t] = idx2[t];
    __syncthreads();

    // In-CTA schedule: stable counting-rank of path t by key idx2 (parallel,
    // fully unrolled 64-compare loop on threads < 64; ~negligible cost).
    if (t < NUM_PATHS) {
        const int p   = t;
        const int key = s_idx2[p];
        int  r    = 0;
        bool last = true;
        #pragma unroll
        for (int q = 0; q < NUM_PATHS; ++q) {
            const int kq = s_idx2[q];
            r    += (kq < key) | ((kq == key) & (q < p));
            last &= !((kq == key) & (q > p));
        }
        s_off0[r] = idx0[p] * SEG_ELEMS;
        s_out[r]  = last ? key * SEG_ELEMS : -1;

        // M[r][i][k] = sum_j x1[b, idx1[p], j] * coeff[p,i,j,k]
        const float* c   = coeff + p * 27;
        const float* x1b = x1 + (size_t)b * (NUM_SEG * D) + idx1[p] * D;
        const float j0 = x1b[0], j1 = x1b[1], j2 = x1b[2];
        #pragma unroll
        for (int i = 0; i < 3; ++i)
            #pragma unroll
            for (int k = 0; k < 3; ++k)
                M[r * 12 + i * 3 + k] =
                    j0 * c[i * 9 + 0 * 3 + k] +
                    j1 * c[i * 9 + 1 * 3 + k] +
                    j2 * c[i * 9 + 2 * 3 + k];
        M[r * 12 +  9] = 0.f;
        M[r * 12 + 10] = 0.f;
        M[r * 12 + 11] = 0.f;
    }
    if (t < NUM_SEG) {
        int c = 0;
        #pragma unroll
        for (int q = 0; q < NUM_PATHS; ++q) c += (s_idx2[q] == t);
        s_emptyoff[t] = (c == 0) ? t * SEG_ELEMS : -1;
    }
    __syncthreads();

    const float*  x0b  = x0  + (size_t)b * ROW_ELEMS;
    float*        outb = out + (size_t)b * ROW_ELEMS;
    const float4* M4   = (const float4*)M;
    const int u3 = t * 3;

    // Flat path loop, R3 structure: plain unroll-4 lets ptxas batch the
    // independent LDGs across iterations (high MLP); register accumulation,
    // direct GMEM store at each segment boundary.
    float f0 = 0.f, f1 = 0.f, f2 = 0.f;
    #pragma unroll 4
    for (int q = 0; q < NUM_PATHS; ++q) {
        const float* xs = x0b + s_off0[q] + u3;
        const float a0 = xs[0];
        const float a1 = xs[1];
        const float a2 = xs[2];
        const float4 m0 = M4[q * 3 + 0];   // M00 M01 M02 M10
        const float4 m1 = M4[q * 3 + 1];   // M11 M12 M20 M21
        const float4 m2 = M4[q * 3 + 2];   // M22 0 0 0
        f0 += a0 * m0.x + a1 * m0.w + a2 * m1.z;
        f1 += a0 * m0.y + a1 * m1.x + a2 * m1.w;
        f2 += a0 * m0.z + a1 * m1.y + a2 * m2.x;
        const int oo = s_out[q];
        if (oo >= 0) {
            float* o = outb + oo + u3;
            o[0] = f0; o[1] = f1; o[2] = f2;
            f0 = 0.f; f1 = 0.f; f2 = 0.f;
        }
    }

    // Zero-fill segments with no paths (output buffer is poisoned).
    #pragma unroll
    for (int s = 0; s < NUM_SEG; ++s) {
        const int eo = s_emptyoff[s];
        if (eo >= 0) {
            float* o = outb + eo + u3;
            o[0] = 0.f; o[1] = 0.f; o[2] = 0.f;
        }
    }
}

extern "C" void kernel_launch(void* const* d_in, const int* in_sizes, int n_in,
                              void* d_out, int out_size)
{
    const float* x0    = (const float*)d_in[0];  // (2048, 12288)
    const float* x1    = (const float*)d_in[1];  // (2048, 96)
    const float* coeff = (const float*)d_in[2];  // (64, 27)
    const int*   idx0  = (const int*)d_in[3];
    const int*   idx1  = (const int*)d_in[4];
    const int*   idx2  = (const int*)d_in[5];
    float*       out   = (float*)d_out;          // (2048, 12288)

    const int batch = in_sizes[0] / ROW_ELEMS;   // 2048

    ftp3_main<<<batch, 128>>>(x0, x1, coeff, idx0, idx1, idx2, out);
}

// round 8
// speedup vs baseline: 1.1271x; 1.0136x over previous
#include <cuda_runtime.h>

#define NUM_SEG   32
#define MUL       128
#define D         3
#define NUM_PATHS 64
#define SEG_ELEMS (MUL * D)              // 384 floats per segment
#define ROW_ELEMS (NUM_SEG * SEG_ELEMS)  // 12288 floats per batch row

__global__ __launch_bounds__(128, 16)    // force <=32 regs: main loop needs no more (R3)
void ftp3_main(const float* __restrict__ x0,
               const float* __restrict__ x1,
               const float* __restrict__ coeff,
               const int*   __restrict__ idx0,
               const int*   __restrict__ idx1,
               const int*   __restrict__ idx2,
               float*       __restrict__ out)
{
    // M padded to 12 floats/path -> LDS.128 broadcast reads.
    __shared__ __align__(16) float M[NUM_PATHS * 12];
    __shared__ int s_idx2[NUM_PATHS];
    __shared__ int s_off0[NUM_PATHS];
    __shared__ int s_out[NUM_PATHS];          // segment-boundary output offset or -1
    __shared__ int s_emptyoff[NUM_SEG];       // offset to zero-fill, or -1

    const int t = threadIdx.x;                // one u per thread
    const int b = blockIdx.x;                 // one batch row per CTA

    if (t < NUM_PATHS) s_idx2[t] = idx2[t];
    __syncthreads();

    // In-CTA schedule: stable counting-rank of path t by key idx2.
    // Rolled loop on purpose: keeps the prologue's live-register set tiny so
    // the 32-reg cap doesn't spill the main loop.
    if (t < NUM_PATHS) {
        const int p   = t;
        const int key = s_idx2[p];
        int r = 0, nlater = 0;
        #pragma unroll 1
        for (int q = 0; q < NUM_PATHS; ++q) {
            const int kq = s_idx2[q];
            r      += (kq < key) | ((kq == key) & (q < p));
            nlater += (kq == key) & (q > p);
        }
        s_off0[r] = idx0[p] * SEG_ELEMS;
        s_out[r]  = (nlater == 0) ? key * SEG_ELEMS : -1;

        // M[r][i][k] = sum_j x1[b, idx1[p], j] * coeff[p,i,j,k]
        const float* c   = coeff + p * 27;
        const float* x1b = x1 + (size_t)b * (NUM_SEG * D) + idx1[p] * D;
        const float j0 = x1b[0], j1 = x1b[1], j2 = x1b[2];
        #pragma unroll
        for (int i = 0; i < 3; ++i)
            #pragma unroll
            for (int k = 0; k < 3; ++k)
                M[r * 12 + i * 3 + k] =
                    j0 * c[i * 9 + 0 * 3 + k] +
                    j1 * c[i * 9 + 1 * 3 + k] +
                    j2 * c[i * 9 + 2 * 3 + k];
        M[r * 12 +  9] = 0.f;
        M[r * 12 + 10] = 0.f;
        M[r * 12 + 11] = 0.f;
    }
    if (t < NUM_SEG) {
        int c = 0;
        #pragma unroll 1
        for (int q = 0; q < NUM_PATHS; ++q) c += (s_idx2[q] == t);
        s_emptyoff[t] = (c == 0) ? t * SEG_ELEMS : -1;
    }
    __syncthreads();

    const float*  x0b  = x0  + (size_t)b * ROW_ELEMS;
    float*        outb = out + (size_t)b * ROW_ELEMS;
    const float4* M4   = (const float4*)M;
    const int u3 = t * 3;

    // Flat path loop (R3 structure): plain unroll-4 lets ptxas batch the
    // independent LDGs across iterations (high MLP); register accumulation,
    // direct GMEM store at each segment boundary.
    float f0 = 0.f, f1 = 0.f, f2 = 0.f;
    #pragma unroll 4
    for (int q = 0; q < NUM_PATHS; ++q) {
        const float* xs = x0b + s_off0[q] + u3;
        const float a0 = xs[0];
        const float a1 = xs[1];
        const float a2 = xs[2];
        const float4 m0 = M4[q * 3 + 0];   // M00 M01 M02 M10
        const float4 m1 = M4[q * 3 + 1];   // M11 M12 M20 M21
        const float4 m2 = M4[q * 3 + 2];   // M22 0 0 0
        f0 += a0 * m0.x + a1 * m0.w + a2 * m1.z;
        f1 += a0 * m0.y + a1 * m1.x + a2 * m1.w;
        f2 += a0 * m0.z + a1 * m1.y + a2 * m2.x;
        const int oo = s_out[q];
        if (oo >= 0) {
            float* o = outb + oo + u3;
            o[0] = f0; o[1] = f1; o[2] = f2;
            f0 = 0.f; f1 = 0.f; f2 = 0.f;
        }
    }

    // Zero-fill segments with no paths (output buffer is poisoned).
    #pragma unroll
    for (int s = 0; s < NUM_SEG; ++s) {
        const int eo = s_emptyoff[s];
        if (eo >= 0) {
            float* o = outb + eo + u3;
            o[0] = 0.f; o[1] = 0.f; o[2] = 0.f;
        }
    }
}

extern "C" void kernel_launch(void* const* d_in, const int* in_sizes, int n_in,
                              void* d_out, int out_size)
{
    const float* x0    = (const float*)d_in[0];  // (2048, 12288)
    const float* x1    = (const float*)d_in[1];  // (2048, 96)
    const float* coeff = (const float*)d_in[2];  // (64, 27)
    const int*   idx0  = (const int*)d_in[3];
    const int*   idx1  = (const int*)d_in[4];
    const int*   idx2  = (const int*)d_in[5];
    float*       out   = (float*)d_out;          // (2048, 12288)

    const int batch = in_sizes[0] / ROW_ELEMS;   // 2048

    ftp3_main<<<batch, 128>>>(x0, x1, coeff, idx0, idx1, idx2, out);
}

// round 9
// speedup vs baseline: 1.3006x; 1.1539x over previous
#include <cuda_runtime.h>

#define NUM_SEG      32
#define MUL          128
#define D            3
#define NUM_PATHS    64
#define SEG_ELEMS    (MUL * D)              // 384 floats per segment
#define ROW_ELEMS    (NUM_SEG * SEG_ELEMS)  // 12288 floats per batch row
#define ROWS_PER_CTA 4                      // one warp per batch row

__global__ __launch_bounds__(128, 4)        // grid-limited occupancy; allow 128 regs
void ftp3_main(const float* __restrict__ x0,
               const float* __restrict__ x1,
               const float* __restrict__ coeff,
               const int*   __restrict__ idx0,
               const int*   __restrict__ idx1,
               const int*   __restrict__ idx2,
               float*       __restrict__ out)
{
    // Per-row M matrices in sorted-path order, padded to 12 floats -> LDS.128.
    __shared__ __align__(16) float M[ROWS_PER_CTA][NUM_PATHS * 12];
    __shared__ int s_idx2[NUM_PATHS];
    __shared__ int s_porder[NUM_PATHS];   // rank -> original path id
    __shared__ int s_x1off[NUM_PATHS];    // rank -> idx1[p]*3
    __shared__ int s_off0[NUM_PATHS];     // rank -> idx0[p]*SEG_ELEMS
    __shared__ int s_out[NUM_PATHS];      // rank -> seg*SEG_ELEMS at boundary, else -1
    __shared__ int s_emptyoff[NUM_SEG];   // seg offset to zero-fill, or -1

    const int t    = threadIdx.x;
    const int w    = t >> 5;              // warp -> row within CTA
    const int lane = t & 31;
    const int b0   = blockIdx.x * ROWS_PER_CTA;

    if (t < NUM_PATHS) s_idx2[t] = idx2[t];
    __syncthreads();

    // Stage 1: threads <64 compute stable counting-rank by idx2 (rolled: tiny
    // register footprint); threads 64..95 find empty segments.
    if (t < NUM_PATHS) {
        const int key = s_idx2[t];
        int r = 0, nlater = 0;
        #pragma unroll 1
        for (int q = 0; q < NUM_PATHS; ++q) {
            const int kq = s_idx2[q];
            r      += (kq < key) | ((kq == key) & (q < t));
            nlater += (kq == key) & (q > t);
        }
        s_porder[r] = t;
        s_x1off[r]  = idx1[t] * D;
        s_off0[r]   = idx0[t] * SEG_ELEMS;
        s_out[r]    = (nlater == 0) ? key * SEG_ELEMS : -1;
    } else if (t < NUM_PATHS + NUM_SEG) {
        const int s = t - NUM_PATHS;
        int c = 0;
        #pragma unroll 1
        for (int q = 0; q < NUM_PATHS; ++q) c += (s_idx2[q] == s);
        s_emptyoff[s] = (c == 0) ? s * SEG_ELEMS : -1;
    }
    __syncthreads();

    // Stage 2: build M for all ROWS_PER_CTA rows x 64 ranks (2 jobs/thread).
    #pragma unroll
    for (int j = t; j < ROWS_PER_CTA * NUM_PATHS; j += 128) {
        const int row = j >> 6;
        const int r   = j & (NUM_PATHS - 1);
        const int p   = s_porder[r];
        const float* c   = coeff + p * 27;                       // [i][j][k]
        const float* x1b = x1 + (size_t)(b0 + row) * (NUM_SEG * D) + s_x1off[r];
        const float j0 = x1b[0], j1 = x1b[1], j2 = x1b[2];
        float* Mr = &M[row][r * 12];
        #pragma unroll
        for (int i = 0; i < 3; ++i)
            #pragma unroll
            for (int k = 0; k < 3; ++k)
                Mr[i * 3 + k] =
                    j0 * c[i * 9 + 0 * 3 + k] +
                    j1 * c[i * 9 + 1 * 3 + k] +
                    j2 * c[i * 9 + 2 * 3 + k];
        Mr[9] = 0.f; Mr[10] = 0.f; Mr[11] = 0.f;
    }
    __syncthreads();

    // Main loop: warp w owns row b0+w; lane owns u = 4*lane .. 4*lane+3,
    // i.e. floats [12*lane, 12*lane+12) of each segment = 3 aligned float4.
    const float*  x0b  = x0  + (size_t)(b0 + w) * ROW_ELEMS;
    float*        outb = out + (size_t)(b0 + w) * ROW_ELEMS;
    const float4* M4   = (const float4*)M[w];
    const int     t3   = lane * 3;        // float4 index within segment

    float acc[12];
    #pragma unroll
    for (int i = 0; i < 12; ++i) acc[i] = 0.f;

    #pragma unroll 4
    for (int q = 0; q < NUM_PATHS; ++q) {
        const float4* xs = (const float4*)(x0b + s_off0[q]) + t3;
        const float4 v0 = xs[0];
        const float4 v1 = xs[1];
        const float4 v2 = xs[2];
        const float a[12] = { v0.x, v0.y, v0.z, v0.w,
                              v1.x, v1.y, v1.z, v1.w,
                              v2.x, v2.y, v2.z, v2.w };

        const float4 q0 = M4[q * 3 + 0];
        const float4 q1 = M4[q * 3 + 1];
        const float4 q2 = M4[q * 3 + 2];
        const float m[9] = { q0.x, q0.y, q0.z, q0.w,
                             q1.x, q1.y, q1.z, q1.w, q2.x };

        #pragma unroll
        for (int u = 0; u < 4; ++u)
            #pragma unroll
            for (int k = 0; k < 3; ++k)
                acc[u * 3 + k] += a[u * 3 + 0] * m[0 + k]
                                + a[u * 3 + 1] * m[3 + k]
                                + a[u * 3 + 2] * m[6 + k];

        const int oo = s_out[q];          // warp-uniform branch
        if (oo >= 0) {
            float4* o = (float4*)(outb + oo) + t3;
            o[0] = make_float4(acc[0], acc[1], acc[2],  acc[3]);
            o[1] = make_float4(acc[4], acc[5], acc[6],  acc[7]);
            o[2] = make_float4(acc[8], acc[9], acc[10], acc[11]);
            #pragma unroll
            for (int i = 0; i < 12; ++i) acc[i] = 0.f;
        }
    }

    // Zero-fill segments with no paths (output buffer is poisoned).
    const float4 z = make_float4(0.f, 0.f, 0.f, 0.f);
    #pragma unroll
    for (int s = 0; s < NUM_SEG; ++s) {
        const int eo = s_emptyoff[s];
        if (eo >= 0) {
            float4* o = (float4*)(outb + eo) + t3;
            o[0] = z; o[1] = z; o[2] = z;
        }
    }
}

extern "C" void kernel_launch(void* const* d_in, const int* in_sizes, int n_in,
                              void* d_out, int out_size)
{
    const float* x0    = (const float*)d_in[0];  // (2048, 12288)
    const float* x1    = (const float*)d_in[1];  // (2048, 96)
    const float* coeff = (const float*)d_in[2];  // (64, 27)
    const int*   idx0  = (const int*)d_in[3];
    const int*   idx1  = (const int*)d_in[4];
    const int*   idx2  = (const int*)d_in[5];
    float*       out   = (float*)d_out;          // (2048, 12288)

    const int batch = in_sizes[0] / ROW_ELEMS;   // 2048
    ftp3_main<<<batch / ROWS_PER_CTA, 128>>>(x0, x1, coeff, idx0, idx1, idx2, out);
}

// round 10
// speedup vs baseline: 1.3356x; 1.0269x over previous
#include <cuda_runtime.h>

#define NUM_SEG      32
#define MUL          128
#define D            3
#define NUM_PATHS    64
#define SEG_ELEMS    (MUL * D)              // 384 floats per segment
#define ROW_ELEMS    (NUM_SEG * SEG_ELEMS)  // 12288 floats per batch row
#define ROWS_PER_CTA 2                      // 2 warps (halves) per batch row

__global__ __launch_bounds__(128, 8)        // cap regs at 64
void ftp3_main(const float* __restrict__ x0,
               const float* __restrict__ x1,
               const float* __restrict__ coeff,
               const int*   __restrict__ idx0,
               const int*   __restrict__ idx1,
               const int*   __restrict__ idx2,
               float*       __restrict__ out)
{
    // Per-row M matrices in sorted-path order, padded to 12 floats -> LDS.128.
    __shared__ __align__(16) float M[ROWS_PER_CTA][NUM_PATHS * 12];
    __shared__ int s_idx2[NUM_PATHS];
    __shared__ int s_key[NUM_PATHS];      // rank -> segment key (sorted)
    __shared__ int s_porder[NUM_PATHS];   // rank -> original path id
    __shared__ int s_x1off[NUM_PATHS];    // rank -> idx1[p]*3
    __shared__ int s_off0[NUM_PATHS];     // rank -> idx0[p]*SEG_ELEMS
    __shared__ int s_out[NUM_PATHS];      // rank -> seg*SEG_ELEMS at boundary, else -1
    __shared__ int s_emptyoff[NUM_SEG];   // seg offset to zero-fill, or -1
    __shared__ int s_split;               // path-list split point (segment-aligned)

    const int t    = threadIdx.x;
    const int w    = t >> 5;
    const int lane = t & 31;
    const int row  = w >> 1;              // 0..1 : row within CTA
    const int half = w & 1;               // 0..1 : which path-range of that row
    const int b0   = blockIdx.x * ROWS_PER_CTA;

    if (t < NUM_PATHS) s_idx2[t] = idx2[t];
    __syncthreads();

    // Stage 1: stable counting-rank of paths by idx2 (rolled: tiny live-set).
    if (t < NUM_PATHS) {
        const int key = s_idx2[t];
        int r = 0, nlater = 0;
        #pragma unroll 1
        for (int q = 0; q < NUM_PATHS; ++q) {
            const int kq = s_idx2[q];
            r      += (kq < key) | ((kq == key) & (q < t));
            nlater += (kq == key) & (q > t);
        }
        s_key[r]    = key;
        s_porder[r] = t;
        s_x1off[r]  = idx1[t] * D;
        s_off0[r]   = idx0[t] * SEG_ELEMS;
        s_out[r]    = (nlater == 0) ? key * SEG_ELEMS : -1;
    } else if (t < NUM_PATHS + NUM_SEG) {
        const int s = t - NUM_PATHS;
        int c = 0;
        #pragma unroll 1
        for (int q = 0; q < NUM_PATHS; ++q) c += (s_idx2[q] == s);
        s_emptyoff[s] = (c == 0) ? s * SEG_ELEMS : -1;
    }
    __syncthreads();

    // Split the sorted path list at the segment boundary nearest rank 32.
    if (t == 0) {
        int best = 0;
        #pragma unroll 1
        for (int r = 1; r <= NUM_PATHS; ++r) {
            const bool bnd = (r == NUM_PATHS) || (s_key[r] != s_key[r - 1]);
            if (bnd && abs(r - 32) < abs(best - 32)) best = r;
        }
        s_split = best;
    }

    // Stage 2: build M for ROWS_PER_CTA rows x 64 ranks (1 job/thread).
    {
        const int r2  = t & (NUM_PATHS - 1);
        const int rw  = t >> 6;
        const int p   = s_porder[r2];
        const float* c   = coeff + p * 27;                       // [i][j][k]
        const float* x1b = x1 + (size_t)(b0 + rw) * (NUM_SEG * D) + s_x1off[r2];
        const float j0 = x1b[0], j1 = x1b[1], j2 = x1b[2];
        float* Mr = &M[rw][r2 * 12];
        #pragma unroll
        for (int i = 0; i < 3; ++i)
            #pragma unroll
            for (int k = 0; k < 3; ++k)
                Mr[i * 3 + k] =
                    j0 * c[i * 9 + 0 * 3 + k] +
                    j1 * c[i * 9 + 1 * 3 + k] +
                    j2 * c[i * 9 + 2 * 3 + k];
        Mr[9] = 0.f; Mr[10] = 0.f; Mr[11] = 0.f;
    }
    __syncthreads();

    // Main loop: warp = (row, half). Lane owns u = 4*lane..4*lane+3, i.e.
    // floats [12*lane, 12*lane+12) of each segment = 3 aligned float4 ->
    // every LDG/STG is a fully-coalesced 512B warp transaction.
    const float*  x0b  = x0  + (size_t)(b0 + row) * ROW_ELEMS;
    float*        outb = out + (size_t)(b0 + row) * ROW_ELEMS;
    const float4* M4   = (const float4*)M[row];
    const int     t3   = lane * 3;

    const int qs = half ? s_split : 0;
    const int qe = half ? NUM_PATHS : s_split;

    float acc[12];
    #pragma unroll
    for (int i = 0; i < 12; ++i) acc[i] = 0.f;

    #pragma unroll 4
    for (int q = qs; q < qe; ++q) {
        const float4* xs = (const float4*)(x0b + s_off0[q]) + t3;
        const float4 v0 = xs[0];
        const float4 v1 = xs[1];
        const float4 v2 = xs[2];
        const float a[12] = { v0.x, v0.y, v0.z, v0.w,
                              v1.x, v1.y, v1.z, v1.w,
                              v2.x, v2.y, v2.z, v2.w };

        const float4 q0 = M4[q * 3 + 0];
        const float4 q1 = M4[q * 3 + 1];
        const float4 q2 = M4[q * 3 + 2];
        const float m[9] = { q0.x, q0.y, q0.z, q0.w,
                             q1.x, q1.y, q1.z, q1.w, q2.x };

        #pragma unroll
        for (int u = 0; u < 4; ++u)
            #pragma unroll
            for (int k = 0; k < 3; ++k)
                acc[u * 3 + k] += a[u * 3 + 0] * m[0 + k]
                                + a[u * 3 + 1] * m[3 + k]
                                + a[u * 3 + 2] * m[6 + k];

        const int oo = s_out[q];          // warp-uniform branch
        if (oo >= 0) {
            float4* o = (float4*)(outb + oo) + t3;
            o[0] = make_float4(acc[0], acc[1], acc[2],  acc[3]);
            o[1] = make_float4(acc[4], acc[5], acc[6],  acc[7]);
            o[2] = make_float4(acc[8], acc[9], acc[10], acc[11]);
            #pragma unroll
            for (int i = 0; i < 12; ++i) acc[i] = 0.f;
        }
    }

    // Zero-fill empty segments (poisoned output); split by segment parity.
    const float4 z = make_float4(0.f, 0.f, 0.f, 0.f);
    #pragma unroll
    for (int s = 0; s < NUM_SEG; ++s) {
        const int eo = s_emptyoff[s];
        if (eo >= 0 && (s & 1) == half) {
            float4* o = (float4*)(outb + eo) + t3;
            o[0] = z; o[1] = z; o[2] = z;
        }
    }
}

extern "C" void kernel_launch(void* const* d_in, const int* in_sizes, int n_in,
                              void* d_out, int out_size)
{
    const float* x0    = (const float*)d_in[0];  // (2048, 12288)
    const float* x1    = (const float*)d_in[1];  // (2048, 96)
    const float* coeff = (const float*)d_in[2];  // (64, 27)
    const int*   idx0  = (const int*)d_in[3];
    const int*   idx1  = (const int*)d_in[4];
    const int*   idx2  = (const int*)d_in[5];
    float*       out   = (float*)d_out;          // (2048, 12288)

    const int batch = in_sizes[0] / ROW_ELEMS;   // 2048
    ftp3_main<<<batch / ROWS_PER_CTA, 128>>>(x0, x1, coeff, idx0, idx1, idx2, out);
}